// round 4
// baseline (speedup 1.0000x reference)
#include <cuda_runtime.h>
#include <cuda_bf16.h>

#define NG    2048
#define W_IMG 128
#define H_IMG 128
#define HW    16384
#define NCHUNK 8          // 2048 / 256 depth chunks
#define NB    128         // blocks (<= 148 SMs: all resident, barrier is safe)
#define NT    128         // threads per block

// ---------------- scratch (static device globals) ----------------------------
__device__ float4 g_p0[NG], g_p1[NG];          // unsorted packed params
__device__ float2 g_p2[NG];                    // (cb, cullR)
__device__ unsigned long long g_key[NG];       // monotone depth key | index
__device__ float4 g_s0[NG], g_s1[NG];          // depth-sorted
__device__ float2 g_s2[NG];

__device__ unsigned g_barcnt = 0;
__device__ volatile unsigned g_bargen = 0;

__device__ __forceinline__ void gridbar() {
    __syncthreads();
    if (threadIdx.x == 0) {
        unsigned gen = g_bargen;
        __threadfence();                      // make this block's writes visible
        unsigned t = atomicAdd(&g_barcnt, 1u);
        if (t == NB - 1) {
            g_barcnt = 0;
            __threadfence();
            g_bargen = gen + 1;               // release
        } else {
            while (g_bargen == gen) { }       // volatile spin
        }
    }
    __syncthreads();
}

__device__ __forceinline__ float ex2(float x) {
    float y;
    asm("ex2.approx.f32 %0, %1;" : "=f"(y) : "f"(x));
    return y;
}
__device__ __forceinline__ float frcp(float x) {
    float y;
    asm("rcp.approx.f32 %0, %1;" : "=f"(y) : "f"(x));
    return y;
}
__device__ __forceinline__ float sig_ap(float x) {
    return frcp(1.0f + ex2(-1.4426950408889634f * x));
}
__device__ __forceinline__ float exp_ap(float x) {
    return ex2(1.4426950408889634f * x);
}
__device__ __forceinline__ unsigned fkey(float f) {
    unsigned u = __float_as_uint(f);
    return (u & 0x80000000u) ? ~u : (u | 0x80000000u);
}

// shared memory union across phases
union SmemU {
    unsigned long long sk[NG];                // rank phase: 16 KB
    struct {
        float4 b0[256];
        float4 b1[256];
        float  b2[256];
        int    wcnt[8];
    } bl;                                     // blend phase: ~9.3 KB
};

__global__ void __launch_bounds__(NT) k_fused(
        const float* __restrict__ pts, const float* __restrict__ scl,
        const float* __restrict__ col, const float* __restrict__ opa,
        const float* __restrict__ rot, const float* __restrict__ view,
        const float* __restrict__ proj, float* __restrict__ out)
{
    __shared__ SmemU sm;
    int tid = threadIdx.x;

    // ================= phase 1: per-gaussian preprocess ======================
    {
        int i = blockIdx.x * NT + tid;
        if (i < NG) {
            float v[16], pr[16];
#pragma unroll
            for (int k = 0; k < 16; k++) v[k]  = view[k];
#pragma unroll
            for (int k = 0; k < 16; k++) pr[k] = proj[k];

            float p0 = pts[3*i], p1 = pts[3*i+1], p2 = pts[3*i+2];

            float t0 = v[0]*p0 + v[1]*p1 + v[2]*p2  + v[3];
            float t1 = v[4]*p0 + v[5]*p1 + v[6]*p2  + v[7];
            float tz = v[8]*p0 + v[9]*p1 + v[10]*p2 + v[11];

            float q0 = rot[4*i], q1 = rot[4*i+1], q2 = rot[4*i+2], q3 = rot[4*i+3];
            float qn = rsqrtf(q0*q0 + q1*q1 + q2*q2 + q3*q3);
            q0 *= qn; q1 *= qn; q2 *= qn; q3 *= qn;
            float R0 = 1.f - 2.f*(q2*q2 + q3*q3), R1 = 2.f*(q1*q2 - q0*q3), R2 = 2.f*(q1*q3 + q0*q2);
            float R3 = 2.f*(q1*q2 + q0*q3), R4 = 1.f - 2.f*(q1*q1 + q3*q3), R5 = 2.f*(q2*q3 - q0*q1);
            float R6 = 2.f*(q1*q3 - q0*q2), R7 = 2.f*(q2*q3 + q0*q1), R8 = 1.f - 2.f*(q1*q1 + q2*q2);

            float s0 = exp_ap(scl[3*i]), s1 = exp_ap(scl[3*i+1]), s2 = exp_ap(scl[3*i+2]);
            float M0 = R0*s0, M1 = R1*s1, M2 = R2*s2;
            float M3 = R3*s0, M4 = R4*s1, M5 = R5*s2;
            float M6 = R6*s0, M7 = R7*s1, M8 = R8*s2;

            const float fx = 64.f, fy = 64.f;
            float invz = frcp(tz);
            float txz = fminf(fmaxf(t0*invz, -1.3f), 1.3f) * tz;
            float tyz = fminf(fmaxf(t1*invz, -1.3f), 1.3f) * tz;
            float J00 = fx*invz, J02 = -fx*txz*invz*invz;
            float J11 = fy*invz, J12 = -fy*tyz*invz*invz;

            float T00 = J00*v[0] + J02*v[8],  T01 = J00*v[1] + J02*v[9],  T02 = J00*v[2] + J02*v[10];
            float T10 = J11*v[4] + J12*v[8],  T11 = J11*v[5] + J12*v[9],  T12 = J11*v[6] + J12*v[10];

            float X00 = T00*M0 + T01*M3 + T02*M6;
            float X01 = T00*M1 + T01*M4 + T02*M7;
            float X02 = T00*M2 + T01*M5 + T02*M8;
            float X10 = T10*M0 + T11*M3 + T12*M6;
            float X11 = T10*M1 + T11*M4 + T12*M7;
            float X12 = T10*M2 + T11*M5 + T12*M8;

            float a = X00*X00 + X01*X01 + X02*X02 + 0.3f;
            float b = X00*X10 + X01*X11 + X02*X12;
            float c = X10*X10 + X11*X11 + X12*X12 + 0.3f;

            float det   = a*c - b*b;
            bool  valid = (tz > 0.2f) && (det > 0.0f);
            float det_s = (det > 0.0f) ? det : 1.0f;
            float idet  = frcp(det_s);

            const float L2E = 1.4426950408889634f;
            float A2 = -0.5f * c * idet * L2E;
            float C2 = -0.5f * a * idet * L2E;
            float Bq =         b * idet * L2E;

            float mid   = 0.5f * (a + c);
            float lam   = mid + sqrtf(fmaxf(mid*mid - det, 0.1f));
            float sq    = sqrtf(lam);
            float radii = valid ? ceilf(3.0f * sq) : 0.0f;
            float cullR = valid ? 3.3294f * sq : 0.0f;   // alpha<1/255 beyond this

            float fr0[4], fr1[4], fr3[4];
#pragma unroll
            for (int cc = 0; cc < 4; cc++) {
                fr0[cc] = pr[0]*v[cc]  + pr[1]*v[4+cc]  + pr[2]*v[8+cc]  + pr[3]*v[12+cc];
                fr1[cc] = pr[4]*v[cc]  + pr[5]*v[4+cc]  + pr[6]*v[8+cc]  + pr[7]*v[12+cc];
                fr3[cc] = pr[12]*v[cc] + pr[13]*v[4+cc] + pr[14]*v[8+cc] + pr[15]*v[12+cc];
            }
            float ph0 = fr0[0]*p0 + fr0[1]*p1 + fr0[2]*p2 + fr0[3];
            float ph1 = fr1[0]*p0 + fr1[1]*p1 + fr1[2]*p2 + fr1[3];
            float ph3 = fr3[0]*p0 + fr3[1]*p1 + fr3[2]*p2 + fr3[3];
            float pwn = frcp(ph3 + 1e-7f);
            float px  = ((ph0*pwn + 1.0f) * (float)W_IMG - 1.0f) * 0.5f;
            float py  = ((ph1*pwn + 1.0f) * (float)H_IMG - 1.0f) * 0.5f;

            float op = valid ? sig_ap(opa[i]) : 0.0f;
            float cr = sig_ap(col[3*i]);
            float cg = sig_ap(col[3*i+1]);
            float cb = sig_ap(col[3*i+2]);

            g_p0[i]  = make_float4(px, py, A2, Bq);
            g_p1[i]  = make_float4(C2, op, cr, cg);
            g_p2[i]  = make_float2(cb, cullR);
            g_key[i] = ((unsigned long long)fkey(tz) << 32) | (unsigned)i;

            out[3*HW + i]      = radii;
            out[3*HW + NG + i] = tz;
        }
    }

    gridbar();

    // ================= phase 2: O(N^2) rank sort + gather ====================
    {
        for (int i = tid; i < NG; i += NT) sm.sk[i] = g_key[i];
        __syncthreads();

        int gt  = blockIdx.x * NT + tid;     // 16384 threads: 8 per gaussian
        int gi  = gt >> 3;
        int sub = gt & 7;
        unsigned long long ki = sm.sk[gi];

        int rk = 0;
#pragma unroll 8
        for (int it = 0; it < NG/8; it++) {
            rk += (sm.sk[8*it + sub] < ki) ? 1 : 0;
        }
        rk += __shfl_xor_sync(0xffffffffu, rk, 1);
        rk += __shfl_xor_sync(0xffffffffu, rk, 2);
        rk += __shfl_xor_sync(0xffffffffu, rk, 4);

        if (sub == 0) {
            g_s0[rk] = g_p0[gi];
            g_s1[rk] = g_p1[gi];
            g_s2[rk] = g_p2[gi];
        }
    }

    gridbar();

    // ================= phase 3: tiled blend (16x8 tile per block) ============
    {
        int wid  = tid >> 5;
        int lane = tid & 31;

        int tx = blockIdx.x & 7;
        int ty = blockIdx.x >> 3;
        int pxi = tx * 16 + (tid & 15);
        int pyi = ty * 8  + (tid >> 4);
        float x = (float)pxi;
        float y = (float)pyi;
        float x0 = (float)(tx * 16), x1 = x0 + 15.f;
        float y0 = (float)(ty * 8),  y1 = y0 + 7.f;

        float r = 0.f, g = 0.f, b = 0.f, T = 1.f;

        float4 A0 = g_s0[tid],       A1 = g_s1[tid];       float2 A2v = g_s2[tid];
        float4 B0 = g_s0[128 + tid], B1 = g_s1[128 + tid]; float2 B2v = g_s2[128 + tid];

        for (int chunk = 0; chunk < NCHUNK; chunk++) {
            float Ra = A2v.y, Rb = B2v.y;
            bool p0 = (Ra > 0.f) && (A0.x + Ra >= x0) && (A0.x - Ra <= x1)
                                 && (A0.y + Ra >= y0) && (A0.y - Ra <= y1);
            bool p1 = (Rb > 0.f) && (B0.x + Rb >= x0) && (B0.x - Rb <= x1)
                                 && (B0.y + Rb >= y0) && (B0.y - Rb <= y1);

            unsigned m0 = __ballot_sync(0xffffffffu, p0);
            unsigned m1 = __ballot_sync(0xffffffffu, p1);
            if (lane == 0) { sm.bl.wcnt[wid] = __popc(m0); sm.bl.wcnt[4 + wid] = __popc(m1); }
            __syncthreads();

            int c0 = sm.bl.wcnt[0], c1 = sm.bl.wcnt[1], c2 = sm.bl.wcnt[2], c3 = sm.bl.wcnt[3];
            int c4 = sm.bl.wcnt[4], c5 = sm.bl.wcnt[5], c6 = sm.bl.wcnt[6], c7 = sm.bl.wcnt[7];
            int tot0 = c0 + c1 + c2 + c3;
            int cnt  = tot0 + c4 + c5 + c6 + c7;
            int pre0 = (wid > 0 ? c0 : 0) + (wid > 1 ? c1 : 0) + (wid > 2 ? c2 : 0);
            int pre1 = tot0 + (wid > 0 ? c4 : 0) + (wid > 1 ? c5 : 0) + (wid > 2 ? c6 : 0);

            if (p0) {
                int pos = pre0 + __popc(m0 & ((1u << lane) - 1u));
                sm.bl.b0[pos] = A0; sm.bl.b1[pos] = A1; sm.bl.b2[pos] = A2v.x;
            }
            if (p1) {
                int pos = pre1 + __popc(m1 & ((1u << lane) - 1u));
                sm.bl.b0[pos] = B0; sm.bl.b1[pos] = B1; sm.bl.b2[pos] = B2v.x;
            }
            __syncthreads();

            if (chunk < NCHUNK - 1) {
                int nb = (chunk + 1) * 256;
                A0 = g_s0[nb + tid];       A1 = g_s1[nb + tid];       A2v = g_s2[nb + tid];
                B0 = g_s0[nb + 128 + tid]; B1 = g_s1[nb + 128 + tid]; B2v = g_s2[nb + 128 + tid];
            }

#pragma unroll 4
            for (int n = 0; n < cnt; n++) {
                float4 c0v = sm.bl.b0[n];
                float4 c1v = sm.bl.b1[n];
                float  cbv = sm.bl.b2[n];
                float dx = x - c0v.x;
                float dy = y - c0v.y;
                float pw = fmaf(c0v.z*dx, dx, fmaf(c1v.x*dy, dy, (c0v.w*dx)*dy));
                float ee = ex2(pw);
                float al = fminf(c1v.y * ee, 0.99f);
                float w  = ((pw <= 0.0f) && (al >= 0.0039215686f)) ? T * al : 0.0f;
                r = fmaf(w, c1v.z, r);
                g = fmaf(w, c1v.w, g);
                b = fmaf(w, cbv,  b);
                T -= w;
            }
            if (__syncthreads_and(T < 1e-4f)) break;
        }

        int p = pyi * W_IMG + pxi;
        out[p]        = r;
        out[HW + p]   = g;
        out[2*HW + p] = b;
    }
}

// ---------------- launch -----------------------------------------------------
extern "C" void kernel_launch(void* const* d_in, const int* in_sizes, int n_in,
                              void* d_out, int out_size)
{
    const float* pts  = (const float*)d_in[0];
    const float* scl  = (const float*)d_in[1];
    const float* col  = (const float*)d_in[2];
    const float* opa  = (const float*)d_in[3];
    const float* rot  = (const float*)d_in[4];
    const float* view = (const float*)d_in[5];
    const float* proj = (const float*)d_in[6];
    float* out = (float*)d_out;

    k_fused<<<NB, NT>>>(pts, scl, col, opa, rot, view, proj, out);
}

// round 5
// speedup vs baseline: 1.4764x; 1.4764x over previous
#include <cuda_runtime.h>
#include <cuda_bf16.h>

#define NG    2048
#define W_IMG 128
#define H_IMG 128
#define HW    16384

// ---------------- scratch (static device globals) ----------------------------
__device__ float4 g_p0[NG], g_p1[NG];          // unsorted packed params
__device__ float2 g_p2[NG];                    // (cb, cullR)
__device__ unsigned long long g_key[NG];       // monotone depth key | index
__device__ float4 g_s0[NG], g_s1[NG];          // depth-sorted
__device__ float2 g_s2[NG];

__device__ __forceinline__ float ex2(float x) {
    float y;
    asm("ex2.approx.f32 %0, %1;" : "=f"(y) : "f"(x));
    return y;
}
__device__ __forceinline__ float frcp(float x) {
    float y;
    asm("rcp.approx.f32 %0, %1;" : "=f"(y) : "f"(x));
    return y;
}
__device__ __forceinline__ float sig_ap(float x) {
    return frcp(1.0f + ex2(-1.4426950408889634f * x));
}
__device__ __forceinline__ float exp_ap(float x) {
    return ex2(1.4426950408889634f * x);
}
__device__ __forceinline__ unsigned fkey(float f) {
    unsigned u = __float_as_uint(f);
    return (u & 0x80000000u) ? ~u : (u | 0x80000000u);
}

// ---------------- 1) per-gaussian preprocess --------------------------------
__global__ void __launch_bounds__(64) k_prep(
        const float* __restrict__ pts, const float* __restrict__ scl,
        const float* __restrict__ col, const float* __restrict__ opa,
        const float* __restrict__ rot, const float* __restrict__ view,
        const float* __restrict__ proj, float* __restrict__ out)
{
    int i = blockIdx.x * 64 + threadIdx.x;
    if (i >= NG) return;

    float v[16], pr[16];
#pragma unroll
    for (int k = 0; k < 16; k++) v[k]  = view[k];
#pragma unroll
    for (int k = 0; k < 16; k++) pr[k] = proj[k];

    float p0 = pts[3*i], p1 = pts[3*i+1], p2 = pts[3*i+2];

    float t0 = v[0]*p0 + v[1]*p1 + v[2]*p2  + v[3];
    float t1 = v[4]*p0 + v[5]*p1 + v[6]*p2  + v[7];
    float tz = v[8]*p0 + v[9]*p1 + v[10]*p2 + v[11];

    float q0 = rot[4*i], q1 = rot[4*i+1], q2 = rot[4*i+2], q3 = rot[4*i+3];
    float qn = rsqrtf(q0*q0 + q1*q1 + q2*q2 + q3*q3);
    q0 *= qn; q1 *= qn; q2 *= qn; q3 *= qn;
    float R0 = 1.f - 2.f*(q2*q2 + q3*q3), R1 = 2.f*(q1*q2 - q0*q3), R2 = 2.f*(q1*q3 + q0*q2);
    float R3 = 2.f*(q1*q2 + q0*q3), R4 = 1.f - 2.f*(q1*q1 + q3*q3), R5 = 2.f*(q2*q3 - q0*q1);
    float R6 = 2.f*(q1*q3 - q0*q2), R7 = 2.f*(q2*q3 + q0*q1), R8 = 1.f - 2.f*(q1*q1 + q2*q2);

    float s0 = exp_ap(scl[3*i]), s1 = exp_ap(scl[3*i+1]), s2 = exp_ap(scl[3*i+2]);
    float M0 = R0*s0, M1 = R1*s1, M2 = R2*s2;
    float M3 = R3*s0, M4 = R4*s1, M5 = R5*s2;
    float M6 = R6*s0, M7 = R7*s1, M8 = R8*s2;

    const float fx = 64.f, fy = 64.f;
    float invz = frcp(tz);
    float txz = fminf(fmaxf(t0*invz, -1.3f), 1.3f) * tz;
    float tyz = fminf(fmaxf(t1*invz, -1.3f), 1.3f) * tz;
    float J00 = fx*invz, J02 = -fx*txz*invz*invz;
    float J11 = fy*invz, J12 = -fy*tyz*invz*invz;

    float T00 = J00*v[0] + J02*v[8],  T01 = J00*v[1] + J02*v[9],  T02 = J00*v[2] + J02*v[10];
    float T10 = J11*v[4] + J12*v[8],  T11 = J11*v[5] + J12*v[9],  T12 = J11*v[6] + J12*v[10];

    float X00 = T00*M0 + T01*M3 + T02*M6;
    float X01 = T00*M1 + T01*M4 + T02*M7;
    float X02 = T00*M2 + T01*M5 + T02*M8;
    float X10 = T10*M0 + T11*M3 + T12*M6;
    float X11 = T10*M1 + T11*M4 + T12*M7;
    float X12 = T10*M2 + T11*M5 + T12*M8;

    float a = X00*X00 + X01*X01 + X02*X02 + 0.3f;
    float b = X00*X10 + X01*X11 + X02*X12;
    float c = X10*X10 + X11*X11 + X12*X12 + 0.3f;

    float det   = a*c - b*b;
    bool  valid = (tz > 0.2f) && (det > 0.0f);
    float det_s = (det > 0.0f) ? det : 1.0f;
    float idet  = frcp(det_s);

    const float L2E = 1.4426950408889634f;
    float A2 = -0.5f * c * idet * L2E;
    float C2 = -0.5f * a * idet * L2E;
    float Bq =         b * idet * L2E;

    float mid   = 0.5f * (a + c);
    float lam   = mid + sqrtf(fmaxf(mid*mid - det, 0.1f));
    float sq    = sqrtf(lam);
    float radii = valid ? ceilf(3.0f * sq) : 0.0f;
    float cullR = valid ? 3.3294f * sq : 0.0f;   // alpha<1/255 guaranteed beyond

    float fr0[4], fr1[4], fr3[4];
#pragma unroll
    for (int cc = 0; cc < 4; cc++) {
        fr0[cc] = pr[0]*v[cc]  + pr[1]*v[4+cc]  + pr[2]*v[8+cc]  + pr[3]*v[12+cc];
        fr1[cc] = pr[4]*v[cc]  + pr[5]*v[4+cc]  + pr[6]*v[8+cc]  + pr[7]*v[12+cc];
        fr3[cc] = pr[12]*v[cc] + pr[13]*v[4+cc] + pr[14]*v[8+cc] + pr[15]*v[12+cc];
    }
    float ph0 = fr0[0]*p0 + fr0[1]*p1 + fr0[2]*p2 + fr0[3];
    float ph1 = fr1[0]*p0 + fr1[1]*p1 + fr1[2]*p2 + fr1[3];
    float ph3 = fr3[0]*p0 + fr3[1]*p1 + fr3[2]*p2 + fr3[3];
    float pwn = frcp(ph3 + 1e-7f);
    float px  = ((ph0*pwn + 1.0f) * (float)W_IMG - 1.0f) * 0.5f;
    float py  = ((ph1*pwn + 1.0f) * (float)H_IMG - 1.0f) * 0.5f;

    float op = valid ? sig_ap(opa[i]) : 0.0f;
    float cr = sig_ap(col[3*i]);
    float cg = sig_ap(col[3*i+1]);
    float cb = sig_ap(col[3*i+2]);

    g_p0[i]  = make_float4(px, py, A2, Bq);
    g_p1[i]  = make_float4(C2, op, cr, cg);
    g_p2[i]  = make_float2(cb, cullR);
    g_key[i] = ((unsigned long long)fkey(tz) << 32) | (unsigned)i;

    out[3*HW + i]      = radii;
    out[3*HW + NG + i] = tz;
}

// ---------------- 2) O(N^2) rank sort (stable, tie-free keys) ----------------
__global__ void __launch_bounds__(256) k_rank()
{
    __shared__ unsigned long long sk[NG];
    int tid = threadIdx.x;
    for (int i = tid; i < NG; i += 256) sk[i] = g_key[i];
    __syncthreads();

    int gt  = blockIdx.x * 256 + tid;
    int gi  = gt >> 3;
    int sub = gt & 7;
    unsigned long long ki = sk[gi];

    int rk = 0;
#pragma unroll 8
    for (int it = 0; it < NG/8; it++) {
        rk += (sk[8*it + sub] < ki) ? 1 : 0;
    }
    rk += __shfl_xor_sync(0xffffffffu, rk, 1);
    rk += __shfl_xor_sync(0xffffffffu, rk, 2);
    rk += __shfl_xor_sync(0xffffffffu, rk, 4);

    if (sub == 0) {
        g_s0[rk] = g_p0[gi];
        g_s1[rk] = g_p1[gi];
        g_s2[rk] = g_p2[gi];
    }
}

// ---------------- 3) depth-split tiled blend ---------------------------------
// 128 blocks x 256 threads. Tile = 16x8 px. Warps 0-3 blend gaussians
// [0,1024) for pixel (tid&127); warps 4-7 blend [1024,2048). Combine:
// rgb = rgb_front + T_front * rgb_back  (alpha compositing is associative).
__global__ void __launch_bounds__(256) k_blend(float* __restrict__ out)
{
    __shared__ float4 fa0[256], fa1[256];
    __shared__ float  fa2[256];
    __shared__ float4 ba0[256], ba1[256];
    __shared__ float  ba2[256];
    __shared__ int    wcnt[16];          // [0..7] front chunk, [8..15] back chunk
    __shared__ float4 comb[128];

    int tid  = threadIdx.x;              // 256
    int wid  = tid >> 5;                 // 0..7
    int lane = tid & 31;
    int half = tid >> 7;                 // 0 = front, 1 = back
    int pix  = tid & 127;

    int tx = blockIdx.x & 7;             // 16 px wide
    int ty = blockIdx.x >> 3;            // 8 px tall
    int pxi = tx * 16 + (pix & 15);
    int pyi = ty * 8  + (pix >> 4);
    float x = (float)pxi;
    float y = (float)pyi;
    float x0 = (float)(tx * 16), x1 = x0 + 15.f;
    float y0 = (float)(ty * 8),  y1 = y0 + 7.f;

    float r = 0.f, g = 0.f, b = 0.f, T = 1.f;

    // prefetch round 0: front chunk 0 (idx tid), back chunk 4 (idx 1024+tid)
    float4 A0 = g_s0[tid],        A1 = g_s1[tid];        float2 A2v = g_s2[tid];
    float4 B0 = g_s0[1024 + tid], B1 = g_s1[1024 + tid]; float2 B2v = g_s2[1024 + tid];

    for (int rr = 0; rr < 4; rr++) {
        float Ra = A2v.y, Rb = B2v.y;
        bool pA = (Ra > 0.f) && (A0.x + Ra >= x0) && (A0.x - Ra <= x1)
                             && (A0.y + Ra >= y0) && (A0.y - Ra <= y1);
        bool pB = (Rb > 0.f) && (B0.x + Rb >= x0) && (B0.x - Rb <= x1)
                             && (B0.y + Rb >= y0) && (B0.y - Rb <= y1);

        unsigned mA = __ballot_sync(0xffffffffu, pA);
        unsigned mB = __ballot_sync(0xffffffffu, pB);
        if (lane == 0) { wcnt[wid] = __popc(mA); wcnt[8 + wid] = __popc(mB); }
        __syncthreads();

        int preA = 0, cntA = 0, preB = 0, cntB = 0;
#pragma unroll
        for (int w2 = 0; w2 < 8; w2++) {
            int ca = wcnt[w2], cbk = wcnt[8 + w2];
            if (w2 < wid) { preA += ca; preB += cbk; }
            cntA += ca; cntB += cbk;
        }
        if (pA) {
            int pos = preA + __popc(mA & ((1u << lane) - 1u));
            fa0[pos] = A0; fa1[pos] = A1; fa2[pos] = A2v.x;
        }
        if (pB) {
            int pos = preB + __popc(mB & ((1u << lane) - 1u));
            ba0[pos] = B0; ba1[pos] = B1; ba2[pos] = B2v.x;
        }
        __syncthreads();

        // prefetch next round
        if (rr < 3) {
            int fa = (rr + 1) * 256;
            int bb = 1024 + (rr + 1) * 256;
            A0 = g_s0[fa + tid]; A1 = g_s1[fa + tid]; A2v = g_s2[fa + tid];
            B0 = g_s0[bb + tid]; B1 = g_s1[bb + tid]; B2v = g_s2[bb + tid];
        }

        const float4* p0 = half ? ba0 : fa0;
        const float4* p1 = half ? ba1 : fa1;
        const float*  p2 = half ? ba2 : fa2;
        int cnt = half ? cntB : cntA;

#pragma unroll 4
        for (int n = 0; n < cnt; n++) {
            float4 c0v = p0[n];
            float4 c1v = p1[n];
            float  cbv = p2[n];
            float dx = x - c0v.x;
            float dy = y - c0v.y;
            float pw = fmaf(c0v.z*dx, dx, fmaf(c1v.x*dy, dy, (c0v.w*dx)*dy));
            float ee = ex2(pw);
            float al = fminf(c1v.y * ee, 0.99f);
            float w  = ((pw <= 0.0f) && (al >= 0.0039215686f)) ? T * al : 0.0f;
            r = fmaf(w, c1v.z, r);
            g = fmaf(w, c1v.w, g);
            b = fmaf(w, cbv,  b);
            T -= w;
        }
        __syncthreads();    // buffers reused next round
    }

    // combine front/back halves
    if (half == 0) comb[pix] = make_float4(r, g, b, T);
    __syncthreads();
    if (half == 1) {
        float4 f = comb[pix];
        int p = pyi * W_IMG + pxi;
        out[p]        = fmaf(f.w, r, f.x);
        out[HW + p]   = fmaf(f.w, g, f.y);
        out[2*HW + p] = fmaf(f.w, b, f.z);
    }
}

// ---------------- launch -----------------------------------------------------
extern "C" void kernel_launch(void* const* d_in, const int* in_sizes, int n_in,
                              void* d_out, int out_size)
{
    const float* pts  = (const float*)d_in[0];
    const float* scl  = (const float*)d_in[1];
    const float* col  = (const float*)d_in[2];
    const float* opa  = (const float*)d_in[3];
    const float* rot  = (const float*)d_in[4];
    const float* view = (const float*)d_in[5];
    const float* proj = (const float*)d_in[6];
    float* out = (float*)d_out;

    k_prep <<<NG/64, 64>>>(pts, scl, col, opa, rot, view, proj, out);
    k_rank <<<64, 256>>>();
    k_blend<<<128, 256>>>(out);
}

// round 6
// speedup vs baseline: 1.6393x; 1.1103x over previous
#include <cuda_runtime.h>
#include <cuda_bf16.h>

#define NG    2048
#define W_IMG 128
#define H_IMG 128
#define HW    16384
#define NB    128         // blocks; <=148 SMs so all co-resident (barrier safe)
#define NT    512         // threads per block

// ---------------- scratch (static device globals) ----------------------------
__device__ float4 g_p0[NG], g_p1[NG];          // unsorted packed params
__device__ float2 g_p2[NG];                    // (cb, cullR)
__device__ unsigned long long g_key[NG];       // monotone depth key | index
__device__ float4 g_s0[NG], g_s1[NG];          // depth-sorted
__device__ float2 g_s2[NG];

__device__ unsigned g_barcnt = 0;
__device__ volatile unsigned g_bargen = 0;

__device__ __forceinline__ void gridbar() {
    __syncthreads();
    if (threadIdx.x == 0) {
        unsigned gen = g_bargen;
        __threadfence();
        unsigned t = atomicAdd(&g_barcnt, 1u);
        if (t == NB - 1) {
            g_barcnt = 0;
            __threadfence();
            g_bargen = gen + 1;
        } else {
            while (g_bargen == gen) { }
        }
    }
    __syncthreads();
}

__device__ __forceinline__ float ex2(float x) {
    float y; asm("ex2.approx.f32 %0, %1;" : "=f"(y) : "f"(x)); return y;
}
__device__ __forceinline__ float frcp(float x) {
    float y; asm("rcp.approx.f32 %0, %1;" : "=f"(y) : "f"(x)); return y;
}
__device__ __forceinline__ float sig_ap(float x) {
    return frcp(1.0f + ex2(-1.4426950408889634f * x));
}
__device__ __forceinline__ float exp_ap(float x) {
    return ex2(1.4426950408889634f * x);
}
__device__ __forceinline__ unsigned fkey(float f) {
    unsigned u = __float_as_uint(f);
    return (u & 0x80000000u) ? ~u : (u | 0x80000000u);
}

// smem: rank keys union blend quarter-buffers
union SmemU {
    unsigned long long sk[NG];                 // 16 KB (rank)
    struct {
        float4 qb0[4][256];                    // 16 KB
        float4 qb1[4][256];                    // 16 KB
        float  qb2[4][256];                    //  4 KB
    } bl;
};

__global__ void __launch_bounds__(NT) k_fused(
        const float* __restrict__ pts, const float* __restrict__ scl,
        const float* __restrict__ col, const float* __restrict__ opa,
        const float* __restrict__ rot, const float* __restrict__ view,
        const float* __restrict__ proj, float* __restrict__ out)
{
    __shared__ SmemU sm;
    __shared__ int    wcnt[32];                // 4 quarters x (4 warps A + 4 warps B)
    __shared__ float4 comb[4][128];

    int tid = threadIdx.x;

    // ================= phase 1: prep (16 gaussians per block) ================
    if (tid < 16) {
        int i = blockIdx.x * 16 + tid;

        float v[16], pr[16];
#pragma unroll
        for (int k = 0; k < 16; k++) v[k]  = view[k];
#pragma unroll
        for (int k = 0; k < 16; k++) pr[k] = proj[k];

        float p0 = pts[3*i], p1 = pts[3*i+1], p2 = pts[3*i+2];

        float t0 = v[0]*p0 + v[1]*p1 + v[2]*p2  + v[3];
        float t1 = v[4]*p0 + v[5]*p1 + v[6]*p2  + v[7];
        float tz = v[8]*p0 + v[9]*p1 + v[10]*p2 + v[11];

        float q0 = rot[4*i], q1 = rot[4*i+1], q2 = rot[4*i+2], q3 = rot[4*i+3];
        float qn = rsqrtf(q0*q0 + q1*q1 + q2*q2 + q3*q3);
        q0 *= qn; q1 *= qn; q2 *= qn; q3 *= qn;
        float R0 = 1.f - 2.f*(q2*q2 + q3*q3), R1 = 2.f*(q1*q2 - q0*q3), R2 = 2.f*(q1*q3 + q0*q2);
        float R3 = 2.f*(q1*q2 + q0*q3), R4 = 1.f - 2.f*(q1*q1 + q3*q3), R5 = 2.f*(q2*q3 - q0*q1);
        float R6 = 2.f*(q1*q3 - q0*q2), R7 = 2.f*(q2*q3 + q0*q1), R8 = 1.f - 2.f*(q1*q1 + q2*q2);

        float s0 = exp_ap(scl[3*i]), s1 = exp_ap(scl[3*i+1]), s2 = exp_ap(scl[3*i+2]);
        float M0 = R0*s0, M1 = R1*s1, M2 = R2*s2;
        float M3 = R3*s0, M4 = R4*s1, M5 = R5*s2;
        float M6 = R6*s0, M7 = R7*s1, M8 = R8*s2;

        const float fx = 64.f, fy = 64.f;
        float invz = frcp(tz);
        float txz = fminf(fmaxf(t0*invz, -1.3f), 1.3f) * tz;
        float tyz = fminf(fmaxf(t1*invz, -1.3f), 1.3f) * tz;
        float J00 = fx*invz, J02 = -fx*txz*invz*invz;
        float J11 = fy*invz, J12 = -fy*tyz*invz*invz;

        float T00 = J00*v[0] + J02*v[8],  T01 = J00*v[1] + J02*v[9],  T02 = J00*v[2] + J02*v[10];
        float T10 = J11*v[4] + J12*v[8],  T11 = J11*v[5] + J12*v[9],  T12 = J11*v[6] + J12*v[10];

        float X00 = T00*M0 + T01*M3 + T02*M6;
        float X01 = T00*M1 + T01*M4 + T02*M7;
        float X02 = T00*M2 + T01*M5 + T02*M8;
        float X10 = T10*M0 + T11*M3 + T12*M6;
        float X11 = T10*M1 + T11*M4 + T12*M7;
        float X12 = T10*M2 + T11*M5 + T12*M8;

        float a = X00*X00 + X01*X01 + X02*X02 + 0.3f;
        float b = X00*X10 + X01*X11 + X02*X12;
        float c = X10*X10 + X11*X11 + X12*X12 + 0.3f;

        float det   = a*c - b*b;
        bool  valid = (tz > 0.2f) && (det > 0.0f);
        float det_s = (det > 0.0f) ? det : 1.0f;
        float idet  = frcp(det_s);

        const float L2E = 1.4426950408889634f;
        float A2 = -0.5f * c * idet * L2E;
        float C2 = -0.5f * a * idet * L2E;
        float Bq =         b * idet * L2E;

        float mid   = 0.5f * (a + c);
        float lam   = mid + sqrtf(fmaxf(mid*mid - det, 0.1f));
        float sq    = sqrtf(lam);
        float radii = valid ? ceilf(3.0f * sq) : 0.0f;
        float cullR = valid ? 3.3294f * sq : 0.0f;

        float fr0[4], fr1[4], fr3[4];
#pragma unroll
        for (int cc = 0; cc < 4; cc++) {
            fr0[cc] = pr[0]*v[cc]  + pr[1]*v[4+cc]  + pr[2]*v[8+cc]  + pr[3]*v[12+cc];
            fr1[cc] = pr[4]*v[cc]  + pr[5]*v[4+cc]  + pr[6]*v[8+cc]  + pr[7]*v[12+cc];
            fr3[cc] = pr[12]*v[cc] + pr[13]*v[4+cc] + pr[14]*v[8+cc] + pr[15]*v[12+cc];
        }
        float ph0 = fr0[0]*p0 + fr0[1]*p1 + fr0[2]*p2 + fr0[3];
        float ph1 = fr1[0]*p0 + fr1[1]*p1 + fr1[2]*p2 + fr1[3];
        float ph3 = fr3[0]*p0 + fr3[1]*p1 + fr3[2]*p2 + fr3[3];
        float pwn = frcp(ph3 + 1e-7f);
        float px  = ((ph0*pwn + 1.0f) * (float)W_IMG - 1.0f) * 0.5f;
        float py  = ((ph1*pwn + 1.0f) * (float)H_IMG - 1.0f) * 0.5f;

        float op = valid ? sig_ap(opa[i]) : 0.0f;
        float cr = sig_ap(col[3*i]);
        float cg = sig_ap(col[3*i+1]);
        float cb = sig_ap(col[3*i+2]);

        g_p0[i]  = make_float4(px, py, A2, Bq);
        g_p1[i]  = make_float4(C2, op, cr, cg);
        g_p2[i]  = make_float2(cb, cullR);
        g_key[i] = ((unsigned long long)fkey(tz) << 32) | (unsigned)i;

        out[3*HW + i]      = radii;
        out[3*HW + NG + i] = tz;
    }

    gridbar();

    // ================= phase 2: rank sort (1 warp per gaussian) ==============
    {
        for (int i = tid; i < NG; i += NT) sm.sk[i] = g_key[i];
        __syncthreads();

        int gt   = blockIdx.x * NT + tid;    // 65536 threads = 2048 warps
        int gi   = gt >> 5;                  // gaussian = global warp id
        int lane = tid & 31;
        unsigned long long ki = sm.sk[gi];

        int rk = 0;
#pragma unroll 16
        for (int it = 0; it < NG/32; it++) {
            rk += (sm.sk[32*it + lane] < ki) ? 1 : 0;
        }
        rk += __shfl_xor_sync(0xffffffffu, rk, 1);
        rk += __shfl_xor_sync(0xffffffffu, rk, 2);
        rk += __shfl_xor_sync(0xffffffffu, rk, 4);
        rk += __shfl_xor_sync(0xffffffffu, rk, 8);
        rk += __shfl_xor_sync(0xffffffffu, rk, 16);

        if (lane == 0) {
            g_s0[rk] = g_p0[gi];
            g_s1[rk] = g_p1[gi];
            g_s2[rk] = g_p2[gi];
        }
    }

    gridbar();

    // ================= phase 3: blend, 4-way depth split =====================
    {
        int lane = tid & 31;
        int qtr  = tid >> 7;                 // 0..3 : gaussian quarter
        int wiq  = (tid >> 5) & 3;           // warp within quarter
        int pix  = tid & 127;

        int tx = blockIdx.x & 7;             // 16 px wide
        int ty = blockIdx.x >> 3;            // 8 px tall
        int pxi = tx * 16 + (pix & 15);
        int pyi = ty * 8  + (pix >> 4);
        float x = (float)pxi;
        float y = (float)pyi;
        float x0 = (float)(tx * 16), x1 = x0 + 15.f;
        float y0 = (float)(ty * 8),  y1 = y0 + 7.f;

        float r = 0.f, g = 0.f, b = 0.f, T = 1.f;

        // each quarter: 512 gaussians = 2 rounds of 256; per round each thread
        // culls 2 gaussians (its warp covers [wiq*32, wiq*32+32) and +128).
        int base0 = qtr * 512;
        int gA = base0 + wiq * 32 + lane;
        int gB = gA + 128;
        float4 A0 = g_s0[gA], A1 = g_s1[gA]; float2 A2v = g_s2[gA];
        float4 B0 = g_s0[gB], B1 = g_s1[gB]; float2 B2v = g_s2[gB];

        for (int rr2 = 0; rr2 < 2; rr2++) {
            float Ra = A2v.y, Rb = B2v.y;
            bool pA = (Ra > 0.f) && (A0.x + Ra >= x0) && (A0.x - Ra <= x1)
                                 && (A0.y + Ra >= y0) && (A0.y - Ra <= y1);
            bool pB = (Rb > 0.f) && (B0.x + Rb >= x0) && (B0.x - Rb <= x1)
                                 && (B0.y + Rb >= y0) && (B0.y - Rb <= y1);

            unsigned mA = __ballot_sync(0xffffffffu, pA);
            unsigned mB = __ballot_sync(0xffffffffu, pB);
            if (lane == 0) {
                wcnt[qtr * 8 + wiq]     = __popc(mA);
                wcnt[qtr * 8 + 4 + wiq] = __popc(mB);
            }
            __syncthreads();

            int totA = 0, preA = 0, preB = 0, cnt = 0;
#pragma unroll
            for (int w2 = 0; w2 < 4; w2++) {
                int ca = wcnt[qtr * 8 + w2];
                int cb2 = wcnt[qtr * 8 + 4 + w2];
                if (w2 < wiq) { preA += ca; preB += cb2; }
                totA += ca; cnt += ca + cb2;
            }
            preB += totA;

            if (pA) {
                int pos = preA + __popc(mA & ((1u << lane) - 1u));
                sm.bl.qb0[qtr][pos] = A0; sm.bl.qb1[qtr][pos] = A1; sm.bl.qb2[qtr][pos] = A2v.x;
            }
            if (pB) {
                int pos = preB + __popc(mB & ((1u << lane) - 1u));
                sm.bl.qb0[qtr][pos] = B0; sm.bl.qb1[qtr][pos] = B1; sm.bl.qb2[qtr][pos] = B2v.x;
            }
            __syncthreads();

            if (rr2 == 0) {
                int nA = base0 + 256 + wiq * 32 + lane;
                int nB = nA + 128;
                A0 = g_s0[nA]; A1 = g_s1[nA]; A2v = g_s2[nA];
                B0 = g_s0[nB]; B1 = g_s1[nB]; B2v = g_s2[nB];
            }

#pragma unroll 4
            for (int n = 0; n < cnt; n++) {
                float4 c0v = sm.bl.qb0[qtr][n];
                float4 c1v = sm.bl.qb1[qtr][n];
                float  cbv = sm.bl.qb2[qtr][n];
                float dx = x - c0v.x;
                float dy = y - c0v.y;
                float pw = fmaf(c0v.z*dx, dx, fmaf(c1v.x*dy, dy, (c0v.w*dx)*dy));
                float ee = ex2(pw);
                float al = fminf(c1v.y * ee, 0.99f);
                float w  = ((pw <= 0.0f) && (al >= 0.0039215686f)) ? T * al : 0.0f;
                r = fmaf(w, c1v.z, r);
                g = fmaf(w, c1v.w, g);
                b = fmaf(w, cbv,  b);
                T -= w;
            }
            __syncthreads();   // buffers reused next round
        }

        // combine quarters: total = c0 + T0*(c1 + T1*(c2 + T2*c3))
        comb[qtr][pix] = make_float4(r, g, b, T);
        __syncthreads();
        if (qtr == 0) {
            float4 c1 = comb[1][pix];
            float4 c2 = comb[2][pix];
            float4 c3 = comb[3][pix];
            float rr = r + T * (c1.x + c1.w * (c2.x + c2.w * c3.x));
            float gg = g + T * (c1.y + c1.w * (c2.y + c2.w * c3.y));
            float bb = b + T * (c1.z + c1.w * (c2.z + c2.w * c3.z));
            int p = pyi * W_IMG + pxi;
            out[p]        = rr;
            out[HW + p]   = gg;
            out[2*HW + p] = bb;
        }
    }
}

// ---------------- launch -----------------------------------------------------
extern "C" void kernel_launch(void* const* d_in, const int* in_sizes, int n_in,
                              void* d_out, int out_size)
{
    const float* pts  = (const float*)d_in[0];
    const float* scl  = (const float*)d_in[1];
    const float* col  = (const float*)d_in[2];
    const float* opa  = (const float*)d_in[3];
    const float* rot  = (const float*)d_in[4];
    const float* view = (const float*)d_in[5];
    const float* proj = (const float*)d_in[6];
    float* out = (float*)d_out;

    k_fused<<<NB, NT>>>(pts, scl, col, opa, rot, view, proj, out);
}

// round 8
// speedup vs baseline: 2.0087x; 1.2253x over previous
#include <cuda_runtime.h>
#include <cuda_bf16.h>

#define NG    2048
#define W_IMG 128
#define H_IMG 128
#define HW    16384
#define NB    256         // blocks; capacity >=4/SM so all co-resident -> barrier safe
#define NT    256         // threads per block

// ---------------- scratch (static device globals) ----------------------------
__device__ float4 g_p0[NG], g_p1[NG];          // unsorted packed params
__device__ float2 g_p2[NG];                    // (cb, cullR)
__device__ unsigned long long g_key[NG];       // monotone depth key | index
__device__ float4 g_s0[NG], g_s1[NG];          // depth-sorted
__device__ float2 g_s2[NG];

__device__ unsigned g_barcnt = 0;
__device__ volatile unsigned g_bargen = 0;

__device__ __forceinline__ void gridbar() {
    __syncthreads();
    if (threadIdx.x == 0) {
        unsigned gen = g_bargen;
        __threadfence();
        unsigned t = atomicAdd(&g_barcnt, 1u);
        if (t == NB - 1) {
            g_barcnt = 0;
            __threadfence();
            g_bargen = gen + 1;
        } else {
            while (g_bargen == gen) { __nanosleep(32); }
        }
    }
    __syncthreads();
}

__device__ __forceinline__ float ex2(float x) {
    float y; asm("ex2.approx.f32 %0, %1;" : "=f"(y) : "f"(x)); return y;
}
__device__ __forceinline__ float frcp(float x) {
    float y; asm("rcp.approx.f32 %0, %1;" : "=f"(y) : "f"(x)); return y;
}
__device__ __forceinline__ float sig_ap(float x) {
    return frcp(1.0f + ex2(-1.4426950408889634f * x));
}
__device__ __forceinline__ float exp_ap(float x) {
    return ex2(1.4426950408889634f * x);
}
__device__ __forceinline__ unsigned fkey(float f) {
    unsigned u = __float_as_uint(f);
    return (u & 0x80000000u) ? ~u : (u | 0x80000000u);
}

// smem: rank keys union blend quarter-buffers
union SmemU {
    unsigned long long sk[NG];                 // 16 KB (rank)
    struct {
        float4 qb0[4][256];                    // 16 KB
        float4 qb1[4][256];                    // 16 KB
        float  qb2[4][256];                    //  4 KB
    } bl;
};

__global__ void __launch_bounds__(NT) k_fused(
        const float* __restrict__ pts, const float* __restrict__ scl,
        const float* __restrict__ col, const float* __restrict__ opa,
        const float* __restrict__ rot, const float* __restrict__ view,
        const float* __restrict__ proj, float* __restrict__ out)
{
    __shared__ SmemU sm;
    __shared__ int    wcnt[4][8];              // per quarter: 4 k-groups x 2 warps
    __shared__ float4 comb[4][64];

    int tid = threadIdx.x;

    // ================= phase 1: prep (8 gaussians per block) =================
    if (tid < 8) {
        int i = blockIdx.x * 8 + tid;

        float v[16], pr[16];
#pragma unroll
        for (int k = 0; k < 16; k++) v[k]  = view[k];
#pragma unroll
        for (int k = 0; k < 16; k++) pr[k] = proj[k];

        float p0 = pts[3*i], p1 = pts[3*i+1], p2 = pts[3*i+2];

        float t0 = v[0]*p0 + v[1]*p1 + v[2]*p2  + v[3];
        float t1 = v[4]*p0 + v[5]*p1 + v[6]*p2  + v[7];
        float tz = v[8]*p0 + v[9]*p1 + v[10]*p2 + v[11];

        float q0 = rot[4*i], q1 = rot[4*i+1], q2 = rot[4*i+2], q3 = rot[4*i+3];
        float qn = rsqrtf(q0*q0 + q1*q1 + q2*q2 + q3*q3);
        q0 *= qn; q1 *= qn; q2 *= qn; q3 *= qn;
        float R0 = 1.f - 2.f*(q2*q2 + q3*q3), R1 = 2.f*(q1*q2 - q0*q3), R2 = 2.f*(q1*q3 + q0*q2);
        float R3 = 2.f*(q1*q2 + q0*q3), R4 = 1.f - 2.f*(q1*q1 + q3*q3), R5 = 2.f*(q2*q3 - q0*q1);
        float R6 = 2.f*(q1*q3 - q0*q2), R7 = 2.f*(q2*q3 + q0*q1), R8 = 1.f - 2.f*(q1*q1 + q2*q2);

        float s0 = exp_ap(scl[3*i]), s1 = exp_ap(scl[3*i+1]), s2 = exp_ap(scl[3*i+2]);
        float M0 = R0*s0, M1 = R1*s1, M2 = R2*s2;
        float M3 = R3*s0, M4 = R4*s1, M5 = R5*s2;
        float M6 = R6*s0, M7 = R7*s1, M8 = R8*s2;

        const float fx = 64.f, fy = 64.f;
        float invz = frcp(tz);
        float txz = fminf(fmaxf(t0*invz, -1.3f), 1.3f) * tz;
        float tyz = fminf(fmaxf(t1*invz, -1.3f), 1.3f) * tz;
        float J00 = fx*invz, J02 = -fx*txz*invz*invz;
        float J11 = fy*invz, J12 = -fy*tyz*invz*invz;

        float T00 = J00*v[0] + J02*v[8],  T01 = J00*v[1] + J02*v[9],  T02 = J00*v[2] + J02*v[10];
        float T10 = J11*v[4] + J12*v[8],  T11 = J11*v[5] + J12*v[9],  T12 = J11*v[6] + J12*v[10];

        float X00 = T00*M0 + T01*M3 + T02*M6;
        float X01 = T00*M1 + T01*M4 + T02*M7;
        float X02 = T00*M2 + T01*M5 + T02*M8;
        float X10 = T10*M0 + T11*M3 + T12*M6;
        float X11 = T10*M1 + T11*M4 + T12*M7;
        float X12 = T10*M2 + T11*M5 + T12*M8;

        float a = X00*X00 + X01*X01 + X02*X02 + 0.3f;
        float b = X00*X10 + X01*X11 + X02*X12;
        float c = X10*X10 + X11*X11 + X12*X12 + 0.3f;

        float det   = a*c - b*b;
        bool  valid = (tz > 0.2f) && (det > 0.0f);
        float det_s = (det > 0.0f) ? det : 1.0f;
        float idet  = frcp(det_s);

        const float L2E = 1.4426950408889634f;
        float A2 = -0.5f * c * idet * L2E;
        float C2 = -0.5f * a * idet * L2E;
        float Bq =         b * idet * L2E;

        float mid   = 0.5f * (a + c);
        float lam   = mid + sqrtf(fmaxf(mid*mid - det, 0.1f));
        float sq    = sqrtf(lam);
        float radii = valid ? ceilf(3.0f * sq) : 0.0f;
        float cullR = valid ? 3.3294f * sq : 0.0f;   // alpha<1/255 beyond this

        float fr0[4], fr1[4], fr3[4];
#pragma unroll
        for (int cc = 0; cc < 4; cc++) {
            fr0[cc] = pr[0]*v[cc]  + pr[1]*v[4+cc]  + pr[2]*v[8+cc]  + pr[3]*v[12+cc];
            fr1[cc] = pr[4]*v[cc]  + pr[5]*v[4+cc]  + pr[6]*v[8+cc]  + pr[7]*v[12+cc];
            fr3[cc] = pr[12]*v[cc] + pr[13]*v[4+cc] + pr[14]*v[8+cc] + pr[15]*v[12+cc];
        }
        float ph0 = fr0[0]*p0 + fr0[1]*p1 + fr0[2]*p2 + fr0[3];
        float ph1 = fr1[0]*p0 + fr1[1]*p1 + fr1[2]*p2 + fr1[3];
        float ph3 = fr3[0]*p0 + fr3[1]*p1 + fr3[2]*p2 + fr3[3];
        float pwn = frcp(ph3 + 1e-7f);
        float px  = ((ph0*pwn + 1.0f) * (float)W_IMG - 1.0f) * 0.5f;
        float py  = ((ph1*pwn + 1.0f) * (float)H_IMG - 1.0f) * 0.5f;

        float op = valid ? sig_ap(opa[i]) : 0.0f;
        float cr = sig_ap(col[3*i]);
        float cg = sig_ap(col[3*i+1]);
        float cb = sig_ap(col[3*i+2]);

        g_p0[i]  = make_float4(px, py, A2, Bq);
        g_p1[i]  = make_float4(C2, op, cr, cg);
        g_p2[i]  = make_float2(cb, cullR);
        g_key[i] = ((unsigned long long)fkey(tz) << 32) | (unsigned)i;

        out[3*HW + i]      = radii;
        out[3*HW + NG + i] = tz;
    }

    gridbar();

    // ================= phase 2: rank sort (1 warp per gaussian) ==============
    {
        for (int i = tid; i < NG; i += NT) sm.sk[i] = g_key[i];
        __syncthreads();

        int gt   = blockIdx.x * NT + tid;    // 65536 threads = 2048 warps
        int gi   = gt >> 5;                  // gaussian = global warp id
        int lane = tid & 31;
        unsigned long long ki = sm.sk[gi];

        int rk = 0;
#pragma unroll 16
        for (int it = 0; it < NG/32; it++) {
            rk += (sm.sk[32*it + lane] < ki) ? 1 : 0;
        }
        rk += __shfl_xor_sync(0xffffffffu, rk, 1);
        rk += __shfl_xor_sync(0xffffffffu, rk, 2);
        rk += __shfl_xor_sync(0xffffffffu, rk, 4);
        rk += __shfl_xor_sync(0xffffffffu, rk, 8);
        rk += __shfl_xor_sync(0xffffffffu, rk, 16);

        if (lane == 0) {
            g_s0[rk] = g_p0[gi];
            g_s1[rk] = g_p1[gi];
            g_s2[rk] = g_p2[gi];
        }
    }

    gridbar();

    // ================= phase 3: blend, 8x8 tile, 4-way depth split ===========
    {
        int lane = tid & 31;
        int qtr  = tid >> 6;                 // 0..3 : gaussian quarter (512 each)
        int wiq  = (tid >> 5) & 1;           // warp within quarter (0/1)
        int pix  = tid & 63;                 // pixel within 8x8 tile

        int tx = blockIdx.x & 15;            // 16 tiles across
        int ty = blockIdx.x >> 4;            // 16 tiles down
        int pxi = tx * 8 + (pix & 7);
        int pyi = ty * 8 + (pix >> 3);
        float x = (float)pxi;
        float y = (float)pyi;
        float x0 = (float)(tx * 8), x1 = x0 + 7.f;
        float y0 = (float)(ty * 8), y1 = y0 + 7.f;

        float r = 0.f, g = 0.f, b = 0.f, T = 1.f;

        int base0 = qtr * 512;

        for (int rr2 = 0; rr2 < 2; rr2++) {
            int rbase = base0 + rr2 * 256;

            // each thread culls 4 gaussians: idx = rbase + k*64 + wiq*32 + lane
            float4 G0[4]; float4 G1[4]; float2 G2[4];
#pragma unroll
            for (int k = 0; k < 4; k++) {
                int gidx = rbase + k * 64 + wiq * 32 + lane;
                G0[k] = g_s0[gidx]; G1[k] = g_s1[gidx]; G2[k] = g_s2[gidx];
            }
            unsigned mk[4];
#pragma unroll
            for (int k = 0; k < 4; k++) {
                float R = G2[k].y;
                bool p = (R > 0.f) && (G0[k].x + R >= x0) && (G0[k].x - R <= x1)
                                   && (G0[k].y + R >= y0) && (G0[k].y - R <= y1);
                mk[k] = __ballot_sync(0xffffffffu, p);
                if (lane == 0) wcnt[qtr][k * 2 + wiq] = __popc(mk[k]);
            }
            __syncthreads();

            // exclusive prefix over (k, wiq) groups, depth order preserved
            int cnts[8];
#pragma unroll
            for (int j = 0; j < 8; j++) cnts[j] = wcnt[qtr][j];
            int cnt = cnts[0] + cnts[1] + cnts[2] + cnts[3]
                    + cnts[4] + cnts[5] + cnts[6] + cnts[7];
#pragma unroll
            for (int k = 0; k < 4; k++) {
                int my = k * 2 + wiq;
                int pre = 0;
#pragma unroll
                for (int j = 0; j < 8; j++) if (j < my) pre += cnts[j];
                unsigned m = mk[k];
                if (m & (1u << lane)) {
                    int pos = pre + __popc(m & ((1u << lane) - 1u));
                    sm.bl.qb0[qtr][pos] = G0[k];
                    sm.bl.qb1[qtr][pos] = G1[k];
                    sm.bl.qb2[qtr][pos] = G2[k].x;
                }
            }
            __syncthreads();

#pragma unroll 4
            for (int n = 0; n < cnt; n++) {
                float4 c0v = sm.bl.qb0[qtr][n];
                float4 c1v = sm.bl.qb1[qtr][n];
                float  cbv = sm.bl.qb2[qtr][n];
                float dx = x - c0v.x;
                float dy = y - c0v.y;
                float pw = fmaf(c0v.z*dx, dx, fmaf(c1v.x*dy, dy, (c0v.w*dx)*dy));
                float ee = ex2(pw);
                float al = fminf(c1v.y * ee, 0.99f);
                float w  = ((pw <= 0.0f) && (al >= 0.0039215686f)) ? T * al : 0.0f;
                r = fmaf(w, c1v.z, r);
                g = fmaf(w, c1v.w, g);
                b = fmaf(w, cbv,  b);
                T -= w;
            }
            __syncthreads();   // buffers reused next round
        }

        // combine quarters: total = c0 + T0*(c1 + T1*(c2 + T2*c3))
        comb[qtr][pix] = make_float4(r, g, b, T);
        __syncthreads();
        if (qtr == 0) {
            float4 c1 = comb[1][pix];
            float4 c2 = comb[2][pix];
            float4 c3 = comb[3][pix];
            float rr = r + T * (c1.x + c1.w * (c2.x + c2.w * c3.x));
            float gg = g + T * (c1.y + c1.w * (c2.y + c2.w * c3.y));
            float bb = b + T * (c1.z + c1.w * (c2.z + c2.w * c3.z));
            int p = pyi * W_IMG + pxi;
            out[p]        = rr;
            out[HW + p]   = gg;
            out[2*HW + p] = bb;
        }
    }
}

// ---------------- launch -----------------------------------------------------
extern "C" void kernel_launch(void* const* d_in, const int* in_sizes, int n_in,
                              void* d_out, int out_size)
{
    const float* pts  = (const float*)d_in[0];
    const float* scl  = (const float*)d_in[1];
    const float* col  = (const float*)d_in[2];
    const float* opa  = (const float*)d_in[3];
    const float* rot  = (const float*)d_in[4];
    const float* view = (const float*)d_in[5];
    const float* proj = (const float*)d_in[6];
    float* out = (float*)d_out;

    k_fused<<<NB, NT>>>(pts, scl, col, opa, rot, view, proj, out);
}